// round 3
// baseline (speedup 1.0000x reference)
#include <cuda_runtime.h>
#include <math.h>
#include <stdint.h>

#define Nn 51200
#define Ee 819200
#define Bb 64

// ---------------- scratch (__device__ globals; allocation-free) ----------------
struct __align__(32) EdgeRec { float4 basis; int src; int widx; int p0; int p1; };

__device__ int     d_cnt[Nn];
__device__ int     d_cur[Nn];
__device__ int     d_off[Nn + 1];
__device__ EdgeRec d_edge[Ee];
__device__ float   d_W1p[192 * 32];          // rows 0..174 = W1 flat, 175..181 = root1, rest 0
__device__ float   d_W2p[832 * 64];          // rows 0..799 = W2 flat, 800..831 = root2
__device__ float   d_U1[(size_t)Nn * 192];
__device__ float   d_h1[(size_t)Nn * 32];
__device__ float   d_U2[(size_t)Nn * 832];
__device__ float   d_h2[(size_t)Nn * 64];

__device__ __forceinline__ float eluf(float v) { return v > 0.f ? v : (expf(v) - 1.f); }

// packed fp32x2 FMA (Blackwell): d = a*b + d, two fp32 lanes per instruction
__device__ __forceinline__ void ffma2(unsigned long long& d, unsigned long long a,
                                      unsigned long long b) {
    asm("fma.rn.f32x2 %0, %1, %2, %0;" : "+l"(d) : "l"(a), "l"(b));
}
__device__ __forceinline__ unsigned long long pack2(float x, float y) {
    unsigned long long r;
    asm("mov.b64 %0, {%1, %2};" : "=l"(r) : "f"(x), "f"(y));
    return r;
}
__device__ __forceinline__ float2 unpk(unsigned long long v) {
    float2 r;
    asm("mov.b64 {%0,%1}, %2;" : "=f"(r.x), "=f"(r.y) : "l"(v));
    return r;
}

// ---------------- CSR build ----------------
__global__ void k_zero() {
    int i = blockIdx.x * blockDim.x + threadIdx.x;
    if (i < Nn) { d_cnt[i] = 0; d_cur[i] = 0; }
}

__global__ void k_hist(const int* __restrict__ dst) {
    int e = blockIdx.x * blockDim.x + threadIdx.x;
    if (e < Ee) atomicAdd(&d_cnt[dst[e]], 1);
}

__global__ void k_scan() {
    __shared__ int s[1024];
    int t = threadIdx.x;
    const int CH = (Nn + 1023) / 1024;  // 50
    int base = t * CH;
    int sum = 0;
    for (int j = 0; j < CH; j++) {
        int idx = base + j;
        if (idx < Nn) sum += d_cnt[idx];
    }
    s[t] = sum;
    __syncthreads();
    for (int ofs = 1; ofs < 1024; ofs <<= 1) {
        int v = (t >= ofs) ? s[t - ofs] : 0;
        __syncthreads();
        if (t >= ofs) s[t] += v;
        __syncthreads();
    }
    int run = (t == 0) ? 0 : s[t - 1];
    for (int j = 0; j < CH; j++) {
        int idx = base + j;
        if (idx < Nn) { d_off[idx] = run; run += d_cnt[idx]; }
    }
    if (t == 1023) d_off[Nn] = run;
}

__global__ void k_scatter(const int* __restrict__ src, const int* __restrict__ dst,
                          const float* __restrict__ pseudo) {
    int e = blockIdx.x * blockDim.x + threadIdx.x;
    if (e >= Ee) return;
    int d = dst[e];
    int pos = d_off[d] + atomicAdd(&d_cur[d], 1);
    float v0 = pseudo[2 * e] * 4.f;
    float v1 = pseudo[2 * e + 1] * 4.f;
    int lo0 = __float2int_rd(v0); lo0 = lo0 < 0 ? 0 : (lo0 > 3 ? 3 : lo0);
    int lo1 = __float2int_rd(v1); lo1 = lo1 < 0 ? 0 : (lo1 > 3 ? 3 : lo1);
    float f0 = v0 - (float)lo0, f1 = v1 - (float)lo1;
    float g0 = 1.f - f0, g1 = 1.f - f1;
    int k0 = lo0 * 5 + lo1;
    int wx = k0 | ((k0 + 1) << 8) | ((k0 + 5) << 16) | ((k0 + 6) << 24);
    *(float4*)&d_edge[pos].basis = make_float4(g0 * g1, g0 * f1, f0 * g1, f0 * f1);
    *(int4*)&d_edge[pos].src = make_int4(src[e], wx, 0, 0);
}

// ---------------- weight prep (fold root into GEMM weights) ----------------
__global__ void k_wprep(const float* __restrict__ W1, const float* __restrict__ root1,
                        const float* __restrict__ W2, const float* __restrict__ root2) {
    int j = blockIdx.x * blockDim.x + threadIdx.x;
    if (j < 192 * 32) {
        float v = 0.f;
        if (j < 5600) v = W1[j];
        else if (j < 5824) v = root1[j - 5600];
        d_W1p[j] = v;
    }
    if (j < 832 * 64) {
        float v;
        if (j < 51200) v = W2[j];
        else v = root2[j - 51200];
        d_W2p[j] = v;
    }
}

// ---------------- U1 build ----------------
__global__ void k_u1(const float* __restrict__ x) {
    __shared__ float su[8][4][176];
    int tid = threadIdx.x;
    int warp = tid >> 5, lane = tid & 31;
    int n = blockIdx.x * 8 + warp;
    if (n >= Nn) return;
    float(*u)[176] = su[warp];
    for (int j = lane; j < 4 * 176; j += 32) ((float*)u)[j] = 0.f;
    __syncwarp();
    int beg = d_off[n], end = d_off[n + 1];
    int eb = lane / 7, i = lane - eb * 7;
    if (lane < 28) {
        for (int p0 = beg; p0 < end; p0 += 4) {
            int p = p0 + eb;
            if (p < end) {
                float4 bs = *(const float4*)&d_edge[p].basis;
                int2 sw = *(const int2*)&d_edge[p].src;
                int sv = sw.x, wx = sw.y;
                float xv = x[sv * 7 + i];
                u[eb][(wx & 255) * 7 + i]         += bs.x * xv;
                u[eb][((wx >> 8) & 255) * 7 + i]  += bs.y * xv;
                u[eb][((wx >> 16) & 255) * 7 + i] += bs.z * xv;
                u[eb][((wx >> 24) & 255) * 7 + i] += bs.w * xv;
            }
        }
    }
    __syncwarp();
    float inv = 1.f / fmaxf((float)(end - beg), 1.f);
    for (int j = lane; j < 192; j += 32) {
        float v;
        if (j < 175)      v = (u[0][j] + u[1][j] + u[2][j] + u[3][j]) * inv;
        else if (j < 182) v = x[n * 7 + (j - 175)];
        else              v = 0.f;
        d_U1[(size_t)n * 192 + j] = v;
    }
}

// ---------------- U2 build ----------------
__global__ void k_u2() {
    __shared__ float su[8][800];
    int tid = threadIdx.x;
    int warp = tid >> 5, lane = tid & 31;
    int n = blockIdx.x * 8 + warp;
    if (n >= Nn) return;
    float* u = su[warp];
    for (int j = lane; j < 800; j += 32) u[j] = 0.f;
    __syncwarp();
    int beg = d_off[n], end = d_off[n + 1];
    for (int p = beg; p < end; p++) {
        float4 bs = *(const float4*)&d_edge[p].basis;
        int2 sw = *(const int2*)&d_edge[p].src;
        int sv = sw.x, wx = sw.y;
        float hv = d_h1[(size_t)sv * 32 + lane];
        u[(wx & 255) * 32 + lane]         += bs.x * hv;
        u[((wx >> 8) & 255) * 32 + lane]  += bs.y * hv;
        u[((wx >> 16) & 255) * 32 + lane] += bs.z * hv;
        u[((wx >> 24) & 255) * 32 + lane] += bs.w * hv;
    }
    __syncwarp();
    float inv = 1.f / fmaxf((float)(end - beg), 1.f);
    for (int j = lane; j < 832; j += 32) {
        float v = (j < 800) ? u[j] * inv : d_h1[(size_t)n * 32 + (j - 800)];
        d_U2[(size_t)n * 832 + j] = v;
    }
}

// ---------------- GEMM1: h1 = elu(U1(N,192) @ W1p(192,32) + b1) ----------------
// 128 thr, tile 128x32, per-thread 8x4, K-chunk 16, W pre-duplicated f32x2 pairs.
__global__ void __launch_bounds__(128) k_gemm1(const float* __restrict__ b1) {
    __shared__ float As[2][16][128];
    __shared__ unsigned long long Wd[2][16][32];  // 16 pairs/k, slot-interleaved
    const int tid = threadIdx.x;
    const int rg = tid >> 3, cg = tid & 7;
    const int m0 = blockIdx.x * 128;
    unsigned long long acc[4][4];
#pragma unroll
    for (int p = 0; p < 4; p++)
#pragma unroll
        for (int c = 0; c < 4; c++) acc[p][c] = 0ULL;
    const float* aRow = &d_U1[(size_t)(m0 + tid) * 192];

#define STG1(BUF, KB)                                                         \
    {                                                                         \
        float4 a0 = *(const float4*)(aRow + (KB));                            \
        float4 a1 = *(const float4*)(aRow + (KB) + 4);                        \
        float4 a2 = *(const float4*)(aRow + (KB) + 8);                        \
        float4 a3 = *(const float4*)(aRow + (KB) + 12);                       \
        As[BUF][0][tid] = a0.x;  As[BUF][1][tid] = a0.y;                      \
        As[BUF][2][tid] = a0.z;  As[BUF][3][tid] = a0.w;                      \
        As[BUF][4][tid] = a1.x;  As[BUF][5][tid] = a1.y;                      \
        As[BUF][6][tid] = a1.z;  As[BUF][7][tid] = a1.w;                      \
        As[BUF][8][tid] = a2.x;  As[BUF][9][tid] = a2.y;                      \
        As[BUF][10][tid] = a2.z; As[BUF][11][tid] = a2.w;                     \
        As[BUF][12][tid] = a3.x; As[BUF][13][tid] = a3.y;                     \
        As[BUF][14][tid] = a3.z; As[BUF][15][tid] = a3.w;                     \
        for (int idx = tid; idx < 256; idx += 128) {                          \
            int k = idx >> 4, p = idx & 15;                                   \
            float2 w = *(const float2*)&d_W1p[((KB) + k) * 32 + 2 * p];       \
            int s = (p & 1) * 8 + (p >> 1);                                   \
            Wd[BUF][k][2 * s]     = pack2(w.x, w.x);                          \
            Wd[BUF][k][2 * s + 1] = pack2(w.y, w.y);                          \
        }                                                                     \
    }

    STG1(0, 0)
    __syncthreads();
    int buf = 0;
    for (int kb = 0; kb < 192; kb += 16) {
        if (kb + 16 < 192) { STG1(buf ^ 1, kb + 16) }
#pragma unroll
        for (int kk = 0; kk < 16; kk++) {
            ulonglong2 aA = *(const ulonglong2*)&As[buf][kk][rg * 8];
            ulonglong2 aB = *(const ulonglong2*)&As[buf][kk][rg * 8 + 4];
            ulonglong2 w01 = *(const ulonglong2*)&Wd[buf][kk][2 * cg];
            ulonglong2 w23 = *(const ulonglong2*)&Wd[buf][kk][2 * (8 + cg)];
            unsigned long long a[4] = {aA.x, aA.y, aB.x, aB.y};
            unsigned long long w[4] = {w01.x, w01.y, w23.x, w23.y};
#pragma unroll
            for (int p = 0; p < 4; p++)
#pragma unroll
                for (int c = 0; c < 4; c++) ffma2(acc[p][c], a[p], w[c]);
        }
        __syncthreads();
        buf ^= 1;
    }
    float4 bv = *(const float4*)&b1[cg * 4];
#pragma unroll
    for (int p = 0; p < 4; p++) {
        float2 c0 = unpk(acc[p][0]), c1 = unpk(acc[p][1]);
        float2 c2 = unpk(acc[p][2]), c3 = unpk(acc[p][3]);
        int row = m0 + rg * 8 + 2 * p;
        float4 lo = make_float4(eluf(c0.x + bv.x), eluf(c1.x + bv.y),
                                eluf(c2.x + bv.z), eluf(c3.x + bv.w));
        float4 hi = make_float4(eluf(c0.y + bv.x), eluf(c1.y + bv.y),
                                eluf(c2.y + bv.z), eluf(c3.y + bv.w));
        *(float4*)&d_h1[(size_t)row * 32 + cg * 4] = lo;
        *(float4*)&d_h1[(size_t)(row + 1) * 32 + cg * 4] = hi;
    }
#undef STG1
}

// ---------------- GEMM2: h2 = elu(U2(N,832) @ W2p(832,64) + b2) ----------------
// 128 thr, tile 128x64, per-thread 8x8, K-chunk 16, W pre-duplicated f32x2 pairs.
__global__ void __launch_bounds__(128) k_gemm2(const float* __restrict__ b2) {
    __shared__ float As[2][16][128];
    __shared__ unsigned long long Wd[2][16][64];  // 32 pairs/k, slot-interleaved
    const int tid = threadIdx.x;
    const int rg = tid >> 3, cg = tid & 7;
    const int m0 = blockIdx.x * 128;
    unsigned long long acc[4][8];
#pragma unroll
    for (int p = 0; p < 4; p++)
#pragma unroll
        for (int c = 0; c < 8; c++) acc[p][c] = 0ULL;
    const float* aRow = &d_U2[(size_t)(m0 + tid) * 832];

#define STG2(BUF, KB)                                                         \
    {                                                                         \
        float4 a0 = *(const float4*)(aRow + (KB));                            \
        float4 a1 = *(const float4*)(aRow + (KB) + 4);                        \
        float4 a2 = *(const float4*)(aRow + (KB) + 8);                        \
        float4 a3 = *(const float4*)(aRow + (KB) + 12);                       \
        As[BUF][0][tid] = a0.x;  As[BUF][1][tid] = a0.y;                      \
        As[BUF][2][tid] = a0.z;  As[BUF][3][tid] = a0.w;                      \
        As[BUF][4][tid] = a1.x;  As[BUF][5][tid] = a1.y;                      \
        As[BUF][6][tid] = a1.z;  As[BUF][7][tid] = a1.w;                      \
        As[BUF][8][tid] = a2.x;  As[BUF][9][tid] = a2.y;                      \
        As[BUF][10][tid] = a2.z; As[BUF][11][tid] = a2.w;                     \
        As[BUF][12][tid] = a3.x; As[BUF][13][tid] = a3.y;                     \
        As[BUF][14][tid] = a3.z; As[BUF][15][tid] = a3.w;                     \
        for (int idx = tid; idx < 512; idx += 128) {                          \
            int k = idx >> 5, p = idx & 31;                                   \
            float2 w = *(const float2*)&d_W2p[((KB) + k) * 64 + 2 * p];       \
            int s = (p & 3) * 8 + (p >> 2);                                   \
            Wd[BUF][k][2 * s]     = pack2(w.x, w.x);                          \
            Wd[BUF][k][2 * s + 1] = pack2(w.y, w.y);                          \
        }                                                                     \
    }

    STG2(0, 0)
    __syncthreads();
    int buf = 0;
    for (int kb = 0; kb < 832; kb += 16) {
        if (kb + 16 < 832) { STG2(buf ^ 1, kb + 16) }
#pragma unroll
        for (int kk = 0; kk < 16; kk++) {
            ulonglong2 aA = *(const ulonglong2*)&As[buf][kk][rg * 8];
            ulonglong2 aB = *(const ulonglong2*)&As[buf][kk][rg * 8 + 4];
            ulonglong2 w01 = *(const ulonglong2*)&Wd[buf][kk][2 * cg];
            ulonglong2 w23 = *(const ulonglong2*)&Wd[buf][kk][2 * (8 + cg)];
            ulonglong2 w45 = *(const ulonglong2*)&Wd[buf][kk][2 * (16 + cg)];
            ulonglong2 w67 = *(const ulonglong2*)&Wd[buf][kk][2 * (24 + cg)];
            unsigned long long a[4] = {aA.x, aA.y, aB.x, aB.y};
            unsigned long long w[8] = {w01.x, w01.y, w23.x, w23.y,
                                       w45.x, w45.y, w67.x, w67.y};
#pragma unroll
            for (int p = 0; p < 4; p++)
#pragma unroll
                for (int c = 0; c < 8; c++) ffma2(acc[p][c], a[p], w[c]);
        }
        __syncthreads();
        buf ^= 1;
    }
    float4 bv0 = *(const float4*)&b2[cg * 8];
    float4 bv1 = *(const float4*)&b2[cg * 8 + 4];
#pragma unroll
    for (int p = 0; p < 4; p++) {
        float2 c0 = unpk(acc[p][0]), c1 = unpk(acc[p][1]);
        float2 c2 = unpk(acc[p][2]), c3 = unpk(acc[p][3]);
        float2 c4 = unpk(acc[p][4]), c5 = unpk(acc[p][5]);
        float2 c6 = unpk(acc[p][6]), c7 = unpk(acc[p][7]);
        int row = m0 + rg * 8 + 2 * p;
        float4 lo0 = make_float4(eluf(c0.x + bv0.x), eluf(c1.x + bv0.y),
                                 eluf(c2.x + bv0.z), eluf(c3.x + bv0.w));
        float4 lo1 = make_float4(eluf(c4.x + bv1.x), eluf(c5.x + bv1.y),
                                 eluf(c6.x + bv1.z), eluf(c7.x + bv1.w));
        float4 hi0 = make_float4(eluf(c0.y + bv0.x), eluf(c1.y + bv0.y),
                                 eluf(c2.y + bv0.z), eluf(c3.y + bv0.w));
        float4 hi1 = make_float4(eluf(c4.y + bv1.x), eluf(c5.y + bv1.y),
                                 eluf(c6.y + bv1.z), eluf(c7.y + bv1.w));
        *(float4*)&d_h2[(size_t)row * 64 + cg * 8] = lo0;
        *(float4*)&d_h2[(size_t)row * 64 + cg * 8 + 4] = lo1;
        *(float4*)&d_h2[(size_t)(row + 1) * 64 + cg * 8] = hi0;
        *(float4*)&d_h2[(size_t)(row + 1) * 64 + cg * 8 + 4] = hi1;
    }
#undef STG2
}

// ---------------- pooling + FC + log_softmax ----------------
__global__ void k_head(const int* __restrict__ slices, const float* __restrict__ fcw,
                       const float* __restrict__ fcb, float* __restrict__ out) {
    int b = blockIdx.x;
    int s0 = slices[b], s1 = slices[b + 1];
    __shared__ float red[4][64];
    __shared__ float g[64];
    __shared__ float lg[30];
    int tid = threadIdx.x;  // 256
    int o = tid & 63, part = tid >> 6;
    float acc = 0.f;
    for (int n = s0 + part; n < s1; n += 4) acc += d_h2[(size_t)n * 64 + o];
    red[part][o] = acc;
    __syncthreads();
    if (part == 0) {
        float s = red[0][o] + red[1][o] + red[2][o] + red[3][o];
        g[o] = s / fmaxf((float)(s1 - s0), 1.f);
    }
    __syncthreads();
    if (tid < 30) {
        float l = fcb[tid];
        for (int i = 0; i < 64; i++) l += g[i] * fcw[i * 30 + tid];
        lg[tid] = l;
    }
    __syncthreads();
    if (tid < 30) {
        float m = -1e30f;
        for (int j = 0; j < 30; j++) m = fmaxf(m, lg[j]);
        float se = 0.f;
        for (int j = 0; j < 30; j++) se += expf(lg[j] - m);
        out[b * 30 + tid] = lg[tid] - m - logf(se);
    }
}

// ---------------- launch ----------------
extern "C" void kernel_launch(void* const* d_in, const int* in_sizes, int n_in,
                              void* d_out, int out_size) {
    const float* x      = (const float*)d_in[0];
    const int*   eidx   = (const int*)d_in[1];
    const float* pseudo = (const float*)d_in[2];
    const int*   slices = (const int*)d_in[3];
    const float* W1     = (const float*)d_in[4];
    const float* root1  = (const float*)d_in[5];
    const float* b1     = (const float*)d_in[6];
    const float* W2     = (const float*)d_in[7];
    const float* root2  = (const float*)d_in[8];
    const float* b2     = (const float*)d_in[9];
    const float* fcw    = (const float*)d_in[10];
    const float* fcb    = (const float*)d_in[11];
    float* out = (float*)d_out;

    const int* src = eidx;
    const int* dst = eidx + Ee;

    k_zero<<<(Nn + 255) / 256, 256>>>();
    k_hist<<<(Ee + 1023) / 1024, 1024>>>(dst);
    k_scan<<<1, 1024>>>();
    k_scatter<<<(Ee + 1023) / 1024, 1024>>>(src, dst, pseudo);
    k_wprep<<<(832 * 64 + 255) / 256, 256>>>(W1, root1, W2, root2);
    k_u1<<<Nn / 8, 256>>>(x);
    k_gemm1<<<Nn / 128, 128>>>(b1);
    k_u2<<<Nn / 8, 256>>>();
    k_gemm2<<<Nn / 128, 128>>>(b2);
    k_head<<<Bb, 256>>>(slices, fcw, fcb, out);
}

// round 4
// speedup vs baseline: 1.5753x; 1.5753x over previous
#include <cuda_runtime.h>
#include <math.h>
#include <stdint.h>

#define Nn 51200
#define Ee 819200
#define Bb 64

typedef unsigned long long ull;

// ---------------- scratch (__device__ globals; allocation-free) ----------------
struct __align__(32) EdgeRec { float4 basis; int src; int widx; int p0; int p1; };

__device__ int     d_cnt[Nn];
__device__ int     d_cur[Nn];
__device__ int     d_off[Nn + 1];
__device__ EdgeRec d_edge[Ee];
__device__ float   d_W1p[192 * 32];          // rows 0..174 = W1 flat, 175..181 = root1, rest 0
__device__ float   d_W2p[832 * 64];          // rows 0..799 = W2 flat, 800..831 = root2
__device__ float   d_U1[(size_t)Nn * 192];
__device__ float   d_h1[(size_t)Nn * 32];
__device__ float   d_U2[(size_t)Nn * 832];
__device__ float   d_h2[(size_t)Nn * 64];

__device__ __forceinline__ float eluf(float v) { return v > 0.f ? v : (expf(v) - 1.f); }

__device__ __forceinline__ void ffma2(ull& d, ull a, ull b) {
    asm("fma.rn.f32x2 %0, %1, %2, %0;" : "+l"(d) : "l"(a), "l"(b));
}
__device__ __forceinline__ ull pack2(float x, float y) {
    ull r;
    asm("mov.b64 %0, {%1, %2};" : "=l"(r) : "f"(x), "f"(y));
    return r;
}
__device__ __forceinline__ float2 unpk(ull v) {
    float2 r;
    asm("mov.b64 {%0,%1}, %2;" : "=f"(r.x), "=f"(r.y) : "l"(v));
    return r;
}

// ---------------- CSR build ----------------
__global__ void k_zero() {
    int i = blockIdx.x * blockDim.x + threadIdx.x;
    if (i < Nn) { d_cnt[i] = 0; d_cur[i] = 0; }
}

__global__ void k_hist(const int* __restrict__ dst) {
    int e = blockIdx.x * blockDim.x + threadIdx.x;
    if (e < Ee) atomicAdd(&d_cnt[dst[e]], 1);
}

__global__ void k_scan() {
    __shared__ int s[1024];
    int t = threadIdx.x;
    const int CH = (Nn + 1023) / 1024;  // 50
    int base = t * CH;
    int sum = 0;
    for (int j = 0; j < CH; j++) {
        int idx = base + j;
        if (idx < Nn) sum += d_cnt[idx];
    }
    s[t] = sum;
    __syncthreads();
    for (int ofs = 1; ofs < 1024; ofs <<= 1) {
        int v = (t >= ofs) ? s[t - ofs] : 0;
        __syncthreads();
        if (t >= ofs) s[t] += v;
        __syncthreads();
    }
    int run = (t == 0) ? 0 : s[t - 1];
    for (int j = 0; j < CH; j++) {
        int idx = base + j;
        if (idx < Nn) { d_off[idx] = run; run += d_cnt[idx]; }
    }
    if (t == 1023) d_off[Nn] = run;
}

__global__ void k_scatter(const int* __restrict__ src, const int* __restrict__ dst,
                          const float* __restrict__ pseudo) {
    int e = blockIdx.x * blockDim.x + threadIdx.x;
    if (e >= Ee) return;
    int d = dst[e];
    int pos = d_off[d] + atomicAdd(&d_cur[d], 1);
    float v0 = pseudo[2 * e] * 4.f;
    float v1 = pseudo[2 * e + 1] * 4.f;
    int lo0 = __float2int_rd(v0); lo0 = lo0 < 0 ? 0 : (lo0 > 3 ? 3 : lo0);
    int lo1 = __float2int_rd(v1); lo1 = lo1 < 0 ? 0 : (lo1 > 3 ? 3 : lo1);
    float f0 = v0 - (float)lo0, f1 = v1 - (float)lo1;
    float g0 = 1.f - f0, g1 = 1.f - f1;
    int k0 = lo0 * 5 + lo1;
    int wx = k0 | ((k0 + 1) << 8) | ((k0 + 5) << 16) | ((k0 + 6) << 24);
    *(float4*)&d_edge[pos].basis = make_float4(g0 * g1, g0 * f1, f0 * g1, f0 * f1);
    *(int4*)&d_edge[pos].src = make_int4(src[e], wx, 0, 0);
}

// ---------------- weight prep (fold root into GEMM weights) ----------------
__global__ void k_wprep(const float* __restrict__ W1, const float* __restrict__ root1,
                        const float* __restrict__ W2, const float* __restrict__ root2) {
    int j = blockIdx.x * blockDim.x + threadIdx.x;
    if (j < 192 * 32) {
        float v = 0.f;
        if (j < 5600) v = W1[j];
        else if (j < 5824) v = root1[j - 5600];
        d_W1p[j] = v;
    }
    if (j < 832 * 64) {
        float v;
        if (j < 51200) v = W2[j];
        else v = root2[j - 51200];
        d_W2p[j] = v;
    }
}

// ---------------- U1 build ----------------
__global__ void k_u1(const float* __restrict__ x) {
    __shared__ float su[8][4][176];
    int tid = threadIdx.x;
    int warp = tid >> 5, lane = tid & 31;
    int n = blockIdx.x * 8 + warp;
    if (n >= Nn) return;
    float(*u)[176] = su[warp];
    for (int j = lane; j < 4 * 176; j += 32) ((float*)u)[j] = 0.f;
    __syncwarp();
    int beg = d_off[n], end = d_off[n + 1];
    int eb = lane / 7, i = lane - eb * 7;
    if (lane < 28) {
        for (int p0 = beg; p0 < end; p0 += 4) {
            int p = p0 + eb;
            if (p < end) {
                float4 bs = *(const float4*)&d_edge[p].basis;
                int2 sw = *(const int2*)&d_edge[p].src;
                int sv = sw.x, wx = sw.y;
                float xv = x[sv * 7 + i];
                u[eb][(wx & 255) * 7 + i]         += bs.x * xv;
                u[eb][((wx >> 8) & 255) * 7 + i]  += bs.y * xv;
                u[eb][((wx >> 16) & 255) * 7 + i] += bs.z * xv;
                u[eb][((wx >> 24) & 255) * 7 + i] += bs.w * xv;
            }
        }
    }
    __syncwarp();
    float inv = 1.f / fmaxf((float)(end - beg), 1.f);
    for (int j = lane; j < 192; j += 32) {
        float v;
        if (j < 175)      v = (u[0][j] + u[1][j] + u[2][j] + u[3][j]) * inv;
        else if (j < 182) v = x[n * 7 + (j - 175)];
        else              v = 0.f;
        d_U1[(size_t)n * 192 + j] = v;
    }
}

// ---------------- U2 build ----------------
__global__ void k_u2() {
    __shared__ float su[8][800];
    int tid = threadIdx.x;
    int warp = tid >> 5, lane = tid & 31;
    int n = blockIdx.x * 8 + warp;
    if (n >= Nn) return;
    float* u = su[warp];
    for (int j = lane; j < 800; j += 32) u[j] = 0.f;
    __syncwarp();
    int beg = d_off[n], end = d_off[n + 1];
    for (int p = beg; p < end; p++) {
        float4 bs = *(const float4*)&d_edge[p].basis;
        int2 sw = *(const int2*)&d_edge[p].src;
        int sv = sw.x, wx = sw.y;
        float hv = d_h1[(size_t)sv * 32 + lane];
        u[(wx & 255) * 32 + lane]         += bs.x * hv;
        u[((wx >> 8) & 255) * 32 + lane]  += bs.y * hv;
        u[((wx >> 16) & 255) * 32 + lane] += bs.z * hv;
        u[((wx >> 24) & 255) * 32 + lane] += bs.w * hv;
    }
    __syncwarp();
    float inv = 1.f / fmaxf((float)(end - beg), 1.f);
    for (int j = lane; j < 832; j += 32) {
        float v = (j < 800) ? u[j] * inv : d_h1[(size_t)n * 32 + (j - 800)];
        d_U2[(size_t)n * 832 + j] = v;
    }
}

// component picker (compile-time constant c under unroll)
#define COMP(F0, F1, c) ((c) == 0 ? (F0).x : (c) == 1 ? (F0).y : (c) == 2 ? (F0).z : (c) == 3 ? (F0).w : \
                         (c) == 4 ? (F1).x : (c) == 5 ? (F1).y : (c) == 6 ? (F1).z : (F1).w)
// 16-element fragment picker: c in 0..15 over four float4s
#define FRAG16(A0, A1, A2, A3, c) ((c) < 8 ? COMP(A0, A1, (c)) : COMP(A2, A3, (c) - 8))

// ---------------- GEMM1 (R1-proven): h1 = elu(U1 @ W1p + b1) ----------------
__global__ void __launch_bounds__(512) k_gemm1(const float* __restrict__ b1) {
    __shared__ float Ws[192 * 32];
    const int tid = threadIdx.x, lane = tid & 31, warp = tid >> 5;
    for (int j = tid; j < 192 * 32 / 4; j += 512)
        ((float4*)Ws)[j] = ((const float4*)d_W1p)[j];
    __syncthreads();
    const int m0 = blockIdx.x * 128 + warp * 8;
    float acc[8];
#pragma unroll
    for (int r = 0; r < 8; r++) acc[r] = 0.f;
    const int rl = lane >> 2, kl = (lane & 3) * 8;
    const float* aBase = &d_U1[(size_t)(m0 + rl) * 192 + kl];
    float4 f0 = *(const float4*)(aBase);
    float4 f1 = *(const float4*)(aBase + 4);
    for (int kb = 0; kb < 192; kb += 32) {
        float4 n0, n1;
        if (kb + 32 < 192) {
            n0 = *(const float4*)(aBase + kb + 32);
            n1 = *(const float4*)(aBase + kb + 36);
        }
#pragma unroll
        for (int kk = 0; kk < 32; kk++) {
            float w = Ws[(kb + kk) * 32 + lane];
            float srcv = COMP(f0, f1, kk & 7);
#pragma unroll
            for (int r = 0; r < 8; r++) {
                float a = __shfl_sync(0xffffffffu, srcv, (r << 2) | (kk >> 3), 32);
                acc[r] += a * w;
            }
        }
        f0 = n0; f1 = n1;
    }
    float bv = b1[lane];
#pragma unroll
    for (int r = 0; r < 8; r++)
        d_h1[(size_t)(m0 + r) * 32 + lane] = eluf(acc[r] + bv);
}

// ---------------- GEMM2 v4: h2 = elu(U2(N,832) @ W2p(832,64) + b2) ----------------
// 256 thr (8 warps), tile 128x64. Warp: 16 rows x 64 cols.
// Lane: rg=lane>>4 (8-row half), cg=lane&15 (4 cols). A in registers + shfl,
// W double-buffered in SMEM (one LDS.128/kk), 16 FFMA2 = 32 MACs per thread-kk.
__global__ void __launch_bounds__(256) k_gemm2(const float* __restrict__ b2) {
    __shared__ float4 Wt[2][512];   // [32 k][64 cols] per buffer
    const int tid = threadIdx.x, lane = tid & 31, warp = tid >> 5;
    const int rg = lane >> 4, cg = lane & 15;
    const int m0 = blockIdx.x * 128;
    const int myrow = m0 + warp * 16 + (lane >> 1);
    const float* aRow = &d_U2[(size_t)myrow * 832 + (lane & 1) * 16];

    ull acc[8][2];
#pragma unroll
    for (int j = 0; j < 8; j++) { acc[j][0] = 0ULL; acc[j][1] = 0ULL; }

    float4 c0 = *(const float4*)(aRow);
    float4 c1 = *(const float4*)(aRow + 4);
    float4 c2 = *(const float4*)(aRow + 8);
    float4 c3 = *(const float4*)(aRow + 12);
    Wt[0][tid]       = ((const float4*)d_W2p)[tid];
    Wt[0][tid + 256] = ((const float4*)d_W2p)[tid + 256];
    __syncthreads();

    int buf = 0;
    for (int kb = 0; kb < 832; kb += 32) {
        float4 n0, n1, n2, n3;
        if (kb + 32 < 832) {
            n0 = *(const float4*)(aRow + kb + 32);
            n1 = *(const float4*)(aRow + kb + 36);
            n2 = *(const float4*)(aRow + kb + 40);
            n3 = *(const float4*)(aRow + kb + 44);
            const float4* wsrc = (const float4*)&d_W2p[(kb + 32) * 64];
            Wt[buf ^ 1][tid]       = wsrc[tid];
            Wt[buf ^ 1][tid + 256] = wsrc[tid + 256];
        }
        const float* wb = (const float*)&Wt[buf][0];
#pragma unroll
        for (int kk = 0; kk < 32; kk++) {
            float fv = FRAG16(c0, c1, c2, c3, kk & 15);
            ulonglong2 w = *(const ulonglong2*)(wb + kk * 64 + cg * 4);
            const int half = (kk >> 4);
#pragma unroll
            for (int j = 0; j < 8; j++) {
                float a = __shfl_sync(0xffffffffu, fv, ((rg * 8 + j) << 1) | half, 32);
                ull a2 = pack2(a, a);
                ffma2(acc[j][0], a2, w.x);
                ffma2(acc[j][1], a2, w.y);
            }
        }
        __syncthreads();
        buf ^= 1;
        c0 = n0; c1 = n1; c2 = n2; c3 = n3;
    }

    float4 bv = *(const float4*)&b2[cg * 4];
#pragma unroll
    for (int j = 0; j < 8; j++) {
        int row = m0 + warp * 16 + rg * 8 + j;
        float2 p0 = unpk(acc[j][0]);
        float2 p1 = unpk(acc[j][1]);
        float4 o = make_float4(eluf(p0.x + bv.x), eluf(p0.y + bv.y),
                               eluf(p1.x + bv.z), eluf(p1.y + bv.w));
        *(float4*)&d_h2[(size_t)row * 64 + cg * 4] = o;
    }
}

// ---------------- pooling + FC + log_softmax ----------------
__global__ void k_head(const int* __restrict__ slices, const float* __restrict__ fcw,
                       const float* __restrict__ fcb, float* __restrict__ out) {
    int b = blockIdx.x;
    int s0 = slices[b], s1 = slices[b + 1];
    __shared__ float red[4][64];
    __shared__ float g[64];
    __shared__ float lg[30];
    int tid = threadIdx.x;  // 256
    int o = tid & 63, part = tid >> 6;
    float acc = 0.f;
    for (int n = s0 + part; n < s1; n += 4) acc += d_h2[(size_t)n * 64 + o];
    red[part][o] = acc;
    __syncthreads();
    if (part == 0) {
        float s = red[0][o] + red[1][o] + red[2][o] + red[3][o];
        g[o] = s / fmaxf((float)(s1 - s0), 1.f);
    }
    __syncthreads();
    if (tid < 30) {
        float l = fcb[tid];
        for (int i = 0; i < 64; i++) l += g[i] * fcw[i * 30 + tid];
        lg[tid] = l;
    }
    __syncthreads();
    if (tid < 30) {
        float m = -1e30f;
        for (int j = 0; j < 30; j++) m = fmaxf(m, lg[j]);
        float se = 0.f;
        for (int j = 0; j < 30; j++) se += expf(lg[j] - m);
        out[b * 30 + tid] = lg[tid] - m - logf(se);
    }
}

// ---------------- launch ----------------
extern "C" void kernel_launch(void* const* d_in, const int* in_sizes, int n_in,
                              void* d_out, int out_size) {
    const float* x      = (const float*)d_in[0];
    const int*   eidx   = (const int*)d_in[1];
    const float* pseudo = (const float*)d_in[2];
    const int*   slices = (const int*)d_in[3];
    const float* W1     = (const float*)d_in[4];
    const float* root1  = (const float*)d_in[5];
    const float* b1     = (const float*)d_in[6];
    const float* W2     = (const float*)d_in[7];
    const float* root2  = (const float*)d_in[8];
    const float* b2     = (const float*)d_in[9];
    const float* fcw    = (const float*)d_in[10];
    const float* fcb    = (const float*)d_in[11];
    float* out = (float*)d_out;

    const int* src = eidx;
    const int* dst = eidx + Ee;

    k_zero<<<(Nn + 255) / 256, 256>>>();
    k_hist<<<(Ee + 1023) / 1024, 1024>>>(dst);
    k_scan<<<1, 1024>>>();
    k_scatter<<<(Ee + 1023) / 1024, 1024>>>(src, dst, pseudo);
    k_wprep<<<(832 * 64 + 255) / 256, 256>>>(W1, root1, W2, root2);
    k_u1<<<Nn / 8, 256>>>(x);
    k_gemm1<<<Nn / 128, 512>>>(b1);
    k_u2<<<Nn / 8, 256>>>();
    k_gemm2<<<Nn / 128, 256>>>(b2);
    k_head<<<Bb, 256>>>(slices, fcw, fcb, out);
}